// round 3
// baseline (speedup 1.0000x reference)
#include <cuda_runtime.h>
#include <stdint.h>

// RNG derivation of jax.random.uniform(key(42), (B,S,A)) 32-bit bits:
// MODE 0: partitionable, first word only        (R1: FAILED, 6.07e-2)
// MODE 2: legacy split-counter                  (R2: FAILED, 6.14e-2)
// MODE 3: partitionable, bits = o0 ^ o1  (jax _threefry_random_bits_partitionable, bit_width 32)
#define RNG_MODE 3

typedef unsigned long long ull;

#define NB   1024      // bs*t
#define SS   16        // SAMPLE
#define AA   8         // N_AGENTS
#define NACT 16        // N_ACTIONS
#define SD   256       // STATE_DIM
#define EM   256       // EMBED
#define NROWS (NB*SS*AA)   // 131072

// scratch (device globals -- no allocation allowed)
__device__ float g_sW1[NB*EM];                 // st@W1_state + b1   (1 MB)
__device__ float g_v[NB];                      // V(s) scalar per batch row
__device__ float g_h1[(size_t)NROWS*EM];       // relu layer-1 activations (134 MB)
__device__ unsigned char g_pos[NROWS];         // pos (argsort) per (b,s,agent)
__device__ float g_adv[NROWS];                 // adv scalar per (b,s,prefix)

// ---------------- threefry2x32 (JAX exact) ----------------
__device__ __forceinline__ uint32_t rotl(uint32_t x, int r){ return (x<<r)|(x>>(32-r)); }

__device__ __forceinline__ void threefry2x32(uint32_t c0, uint32_t c1, uint32_t &o0, uint32_t &o1){
  // key = jax.random.key(42) -> (k1, k2) = (0, 42)
  const uint32_t k0 = 0u, k1v = 42u, k2 = 0u ^ 42u ^ 0x1BD11BDAu;
  uint32_t x0 = c0 + k0;
  uint32_t x1 = c1 + k1v;
#define TF_R(rot) { x0 += x1; x1 = rotl(x1, rot); x1 ^= x0; }
  TF_R(13) TF_R(15) TF_R(26) TF_R(6)
  x0 += k1v; x1 += k2 + 1u;
  TF_R(17) TF_R(29) TF_R(16) TF_R(24)
  x0 += k2;  x1 += k0 + 2u;
  TF_R(13) TF_R(15) TF_R(26) TF_R(6)
  x0 += k0;  x1 += k1v + 3u;
  TF_R(17) TF_R(29) TF_R(16) TF_R(24)
  x0 += k1v; x1 += k2 + 4u;
  TF_R(13) TF_R(15) TF_R(26) TF_R(6)
  x0 += k2;  x1 += k0 + 5u;
#undef TF_R
  o0 = x0; o1 = x1;
}

__device__ __forceinline__ float bits_to_unit(uint32_t bits){
  // jax _uniform for float32: bitcast(0x3f800000 | (bits>>9)) - 1.0
  return __uint_as_float(0x3f800000u | (bits >> 9)) - 1.0f;
}

// ---------------- f32x2 packed FMA helpers ----------------
__device__ __forceinline__ ull pack2(float x){
  ull r; unsigned u = __float_as_uint(x);
  asm("mov.b64 %0, {%1,%1};" : "=l"(r) : "r"(u));
  return r;
}
__device__ __forceinline__ void fma2(ull& d, ull a, ull b){
  asm("fma.rn.f32x2 %0, %1, %2, %0;" : "+l"(d) : "l"(a), "l"(b));
}
__device__ __forceinline__ float2 unpack2(ull v){
  unsigned lo, hi; asm("mov.b64 {%0,%1}, %2;" : "=r"(lo), "=r"(hi) : "l"(v));
  return make_float2(__uint_as_float(lo), __uint_as_float(hi));
}

// ============ K1: per-b state terms: sW1 = st@W1[:256]+b1 ; v = relu(st@Vw1+Vb1)@Vw2+Vb2 ============
__global__ void k1_state(const float* __restrict__ st, const float* __restrict__ W1,
                         const float* __restrict__ b1, const float* __restrict__ Vw1,
                         const float* __restrict__ Vb1, const float* __restrict__ Vw2,
                         const float* __restrict__ Vb2){
  int b = blockIdx.x, n = threadIdx.x;
  __shared__ float s_st[SD];
  __shared__ float red[EM];
  s_st[n] = st[b*SD + n];
  __syncthreads();
  float acc  = b1[n];
  float accv = Vb1[n];
  #pragma unroll 8
  for(int k=0;k<SD;k++){
    float sv = s_st[k];
    acc  = fmaf(sv, W1 [k*EM + n], acc);
    accv = fmaf(sv, Vw1[k*EM + n], accv);
  }
  g_sW1[b*EM + n] = acc;
  red[n] = fmaxf(accv, 0.f) * Vw2[n];
  __syncthreads();
  for(int off=128; off>0; off>>=1){
    if(n<off) red[n] += red[n+off];
    __syncthreads();
  }
  if(n==0) g_v[b] = red[0] + Vb2[0];
}

// ============ K2: RNG + permutations + prefix layer-1 ============
__global__ void k2_layer1(const float* __restrict__ qs, const float* __restrict__ W1){
  int b = blockIdx.x;
  int tid = threadIdx.x;
  __shared__ int   s_inv[SS][AA];
  __shared__ float s_rq[SS*AA*NACT]; // reordered q values: rq[s][j][na] = qs[b, inv[j], na]

  if(tid < SS){
    int s = tid;
    unsigned base = (unsigned)((b*SS + s)*AA);
    float u[AA];
    #pragma unroll
    for(int a=0;a<AA;a++){
      unsigned g = base + a;
      uint32_t o0, o1, bits;
#if RNG_MODE==0
      threefry2x32(0u, g, o0, o1); bits = o0;
#elif RNG_MODE==1
      threefry2x32(0u, g, o0, o1); bits = o1;
#elif RNG_MODE==2
      if(g < 65536u){ threefry2x32(g, g + 65536u, o0, o1); bits = o0; }
      else          { threefry2x32(g - 65536u, g, o0, o1); bits = o1; }
#else
      threefry2x32(0u, g, o0, o1); bits = o0 ^ o1;
#endif
      u[a] = bits_to_unit(bits);
    }
    // stable ascending argsort of 8 values
    int ord[AA];
    #pragma unroll
    for(int i=0;i<AA;i++) ord[i]=i;
    for(int i=1;i<AA;i++){
      int oi = ord[i]; float ku = u[oi]; int j=i;
      while(j>0 && u[ord[j-1]] > ku){ ord[j]=ord[j-1]; j--; }
      ord[j]=oi;
    }
    #pragma unroll
    for(int r=0;r<AA;r++) s_inv[s][ord[r]] = r;
    #pragma unroll
    for(int i=0;i<AA;i++) g_pos[base + i] = (unsigned char)ord[i];
  }
  __syncthreads();
  for(int e=tid; e<SS*AA*NACT; e+=blockDim.x){
    int s  = e >> 7;
    int r  = e & 127;
    int j  = r >> 4;
    int na = r & 15;
    s_rq[e] = qs[b*(AA*NACT) + s_inv[s][j]*NACT + na];
  }
  __syncthreads();

  // 256 threads: 4 s-groups x 64 col-groups (4 cols each). Each thread: 4 s x 4 cols accumulators.
  int sgrp = tid >> 6;
  int cg   = tid & 63;
  const float4 base4 = *(const float4*)&g_sW1[b*EM + cg*4];
  float4 acc[4];
  #pragma unroll
  for(int sl=0;sl<4;sl++) acc[sl] = base4;

  for(int j=0;j<AA;j++){
    #pragma unroll
    for(int na=0;na<NACT;na++){
      float4 w = *(const float4*)&W1[(SD + j*NACT + na)*EM + cg*4];
      #pragma unroll
      for(int sl=0;sl<4;sl++){
        float q = s_rq[(sgrp*4+sl)*128 + j*16 + na];  // warp-uniform -> LDS broadcast
        acc[sl].x = fmaf(q, w.x, acc[sl].x);
        acc[sl].y = fmaf(q, w.y, acc[sl].y);
        acc[sl].z = fmaf(q, w.z, acc[sl].z);
        acc[sl].w = fmaf(q, w.w, acc[sl].w);
      }
    }
    // prefix point j: emit relu rows
    #pragma unroll
    for(int sl=0;sl<4;sl++){
      int s = sgrp*4+sl;
      size_t row = (size_t)((b*SS+s)*AA + j);
      float4 o;
      o.x = fmaxf(acc[sl].x, 0.f); o.y = fmaxf(acc[sl].y, 0.f);
      o.z = fmaxf(acc[sl].z, 0.f); o.w = fmaxf(acc[sl].w, 0.f);
      *(float4*)&g_h1[row*EM + cg*4] = o;
    }
  }
}

// ============ K3: fused GEMM2 + W3 projection ============
__global__ void __launch_bounds__(256,2) k3_gemm2(const float* __restrict__ W2,
                  const float* __restrict__ b2, const float* __restrict__ W3,
                  const float* __restrict__ b3){
  const int m0  = blockIdx.x * 128;
  const int tid = threadIdx.x;
  const int tx  = tid & 15;
  const int ty  = tid >> 4;
  __shared__ __align__(16) float Hs[128][8];
  __shared__ __align__(16) float Ws[8][128];
  __shared__ float sred[128][17];

  float partial[8];
  #pragma unroll
  for(int i=0;i<8;i++) partial[i]=0.f;

  for(int nh=0; nh<2; nh++){
    const int n0 = nh*128;
    ull acc[8][4];
    #pragma unroll
    for(int i=0;i<8;i++){
      #pragma unroll
      for(int j=0;j<4;j++) acc[i][j]=0ull;
    }

    for(int ks=0; ks<256; ks+=8){
      __syncthreads();
      {
        int r = tid >> 1, kq = (tid & 1)*4;
        float4 v = *(const float4*)&g_h1[(size_t)(m0+r)*EM + ks + kq];
        *(float4*)&Hs[r][kq] = v;
      }
      {
        int k = tid >> 5, c = (tid & 31)*4;
        float4 v = *(const float4*)&W2[(ks+k)*EM + n0 + c];
        *(float4*)&Ws[k][c] = v;
      }
      __syncthreads();
      #pragma unroll
      for(int kk=0;kk<8;kk++){
        ull bfr[4];
        const ull* wp = (const ull*)&Ws[kk][tx*8];
        #pragma unroll
        for(int j=0;j<4;j++) bfr[j]=wp[j];
        #pragma unroll
        for(int i=0;i<8;i++){
          ull a2 = pack2(Hs[ty*8+i][kk]);
          #pragma unroll
          for(int j=0;j<4;j++) fma2(acc[i][j], a2, bfr[j]);
        }
      }
    }
    // epilogue for this n-half: relu(acc + b2) dot W3
    #pragma unroll
    for(int j=0;j<4;j++){
      int n = n0 + tx*8 + j*2;
      float2 bb = *(const float2*)&b2[n];
      float2 w3 = *(const float2*)&W3[n];
      #pragma unroll
      for(int i=0;i<8;i++){
        float2 y = unpack2(acc[i][j]);
        partial[i] += fmaxf(y.x+bb.x, 0.f)*w3.x + fmaxf(y.y+bb.y, 0.f)*w3.y;
      }
    }
  }
  __syncthreads();
  #pragma unroll
  for(int i=0;i<8;i++) sred[ty*8+i][tx] = partial[i];
  __syncthreads();
  if(tid < 128){
    float ssum = b3[0];
    #pragma unroll
    for(int t=0;t<16;t++) ssum += sred[tid][t];
    g_adv[m0 + tid] = ssum;
  }
}

// ============ K4: shapley[b,i] = v[b] + mean_s adv[b,s,pos[b,s,i]] ============
__global__ void k4_out(float* __restrict__ out){
  int idx = blockIdx.x*blockDim.x + threadIdx.x;
  if(idx >= NB*AA) return;
  int b = idx >> 3, i = idx & 7;
  float sum = 0.f;
  #pragma unroll
  for(int s=0;s<SS;s++){
    int base = (b*SS+s)*AA;
    sum += g_adv[base + (int)g_pos[base+i]];
  }
  out[idx] = g_v[b] + sum * (1.0f/16.0f);
}

extern "C" void kernel_launch(void* const* d_in, const int* in_sizes, int n_in,
                              void* d_out, int out_size){
  const float* states   = (const float*)d_in[0];
  const float* agent_qs = (const float*)d_in[1];
  const float* W1  = (const float*)d_in[2];
  const float* b1  = (const float*)d_in[3];
  const float* W2  = (const float*)d_in[4];
  const float* b2  = (const float*)d_in[5];
  const float* W3  = (const float*)d_in[6];
  const float* b3  = (const float*)d_in[7];
  const float* Vw1 = (const float*)d_in[8];
  const float* Vb1 = (const float*)d_in[9];
  const float* Vw2 = (const float*)d_in[10];
  const float* Vb2 = (const float*)d_in[11];
  float* out = (float*)d_out;

  k1_state <<<NB, EM>>>(states, W1, b1, Vw1, Vb1, Vw2, Vb2);
  k2_layer1<<<NB, 256>>>(agent_qs, W1);
  k3_gemm2 <<<NROWS/128, 256>>>(W2, b2, W3, b3);
  k4_out   <<<(NB*AA + 255)/256, 256>>>(out);
}

// round 5
// speedup vs baseline: 2.1923x; 2.1923x over previous
#include <cuda_runtime.h>
#include <cuda_bf16.h>
#include <stdint.h>

#define RNG_MODE 3   // partitionable, bits = o0 ^ o1 (confirmed R3)

typedef unsigned long long ull;

#define NB   1024
#define SS   16
#define AA   8
#define NACT 16
#define SD   256
#define EM   256
#define NROWS (NB*SS*AA)   // 131072

// ---------------- device scratch (no allocation allowed) ----------------
__device__ float g_sW1[NB*EM];
__device__ float g_v[NB];
__device__ unsigned char g_pos[NROWS];
__device__ float g_adv[NROWS];
// h1 in mma.m16n8k16 A-fragment layout, bf16 hi/lo:
// [b][mblk(8)][kblk(16)][lane(32)][reg(4)] u32  -> 64 MB each
__device__ uint32_t g_Ah[(size_t)NB*8*16*32*4];
__device__ uint32_t g_Al[(size_t)NB*8*16*32*4];
// W2 in B-fragment layout: [kblk(16)][nblk(32)][lane(32)][reg(2)] u32 -> 128 KB each
__device__ uint32_t g_Bh[16*32*32*2];
__device__ uint32_t g_Bl[16*32*32*2];

// ---------------- threefry2x32 (JAX exact, key(42)) ----------------
__device__ __forceinline__ uint32_t rotl(uint32_t x, int r){ return (x<<r)|(x>>(32-r)); }
__device__ __forceinline__ void threefry2x32(uint32_t c0, uint32_t c1, uint32_t &o0, uint32_t &o1){
  const uint32_t k0 = 0u, k1v = 42u, k2 = 0u ^ 42u ^ 0x1BD11BDAu;
  uint32_t x0 = c0 + k0;
  uint32_t x1 = c1 + k1v;
#define TF_R(rot) { x0 += x1; x1 = rotl(x1, rot); x1 ^= x0; }
  TF_R(13) TF_R(15) TF_R(26) TF_R(6)
  x0 += k1v; x1 += k2 + 1u;
  TF_R(17) TF_R(29) TF_R(16) TF_R(24)
  x0 += k2;  x1 += k0 + 2u;
  TF_R(13) TF_R(15) TF_R(26) TF_R(6)
  x0 += k0;  x1 += k1v + 3u;
  TF_R(17) TF_R(29) TF_R(16) TF_R(24)
  x0 += k1v; x1 += k2 + 4u;
  TF_R(13) TF_R(15) TF_R(26) TF_R(6)
  x0 += k2;  x1 += k0 + 5u;
#undef TF_R
  o0 = x0; o1 = x1;
}
__device__ __forceinline__ float bits_to_unit(uint32_t bits){
  return __uint_as_float(0x3f800000u | (bits >> 9)) - 1.0f;
}

__device__ __forceinline__ void split_bf16(float v, uint32_t &h, uint32_t &l){
  __nv_bfloat16 hb = __float2bfloat16(v);
  float lf = v - __bfloat162float(hb);
  __nv_bfloat16 lb = __float2bfloat16(lf);
  h = (uint32_t)__bfloat16_as_ushort(hb);
  l = (uint32_t)__bfloat16_as_ushort(lb);
}

// mma.sync m16n8k16 row.col f32.bf16.bf16.f32, D += A*B
__device__ __forceinline__ void mma16816(float* d, const uint32_t* a, uint32_t b0, uint32_t b1){
  asm volatile("mma.sync.aligned.m16n8k16.row.col.f32.bf16.bf16.f32 "
    "{%0,%1,%2,%3}, {%4,%5,%6,%7}, {%8,%9}, {%0,%1,%2,%3};"
    : "+f"(d[0]),"+f"(d[1]),"+f"(d[2]),"+f"(d[3])
    : "r"(a[0]),"r"(a[1]),"r"(a[2]),"r"(a[3]), "r"(b0),"r"(b1));
}

// ============ K0: W2 -> B-fragment bf16 hi/lo ============
// B frag (k x n, col fragment): b_reg holds k-pair; lane = (n%8)*4 + (k%8)/2;
// reg = (k%16)/8; lower halfword = even k.
__global__ void k0_prepW2(const float* __restrict__ W2){
  int idx = blockIdx.x*256 + threadIdx.x;   // 32768
  int kp = idx >> 8, n = idx & 255;
  int k = kp*2;
  float v0 = W2[k*EM + n];
  float v1 = W2[(k+1)*EM + n];
  uint32_t h0,l0,h1,l1;
  split_bf16(v0,h0,l0); split_bf16(v1,h1,l1);
  uint32_t hi = h0 | (h1<<16);
  uint32_t lo = l0 | (l1<<16);
  int kblk = kp>>3;
  int reg  = (kp>>2)&1;
  int lane = (n&7)*4 + (kp&3);
  int nblk = n>>3;
  int bidx = ((kblk*32+nblk)*32+lane)*2 + reg;
  g_Bh[bidx] = hi;
  g_Bl[bidx] = lo;
}

// ============ K1: per-b state terms ============
__global__ void k1_state(const float* __restrict__ st, const float* __restrict__ W1,
                         const float* __restrict__ b1, const float* __restrict__ Vw1,
                         const float* __restrict__ Vb1, const float* __restrict__ Vw2,
                         const float* __restrict__ Vb2){
  int b = blockIdx.x, n = threadIdx.x;
  __shared__ float s_st[SD];
  __shared__ float red[EM];
  s_st[n] = st[b*SD + n];
  __syncthreads();
  float acc  = b1[n];
  float accv = Vb1[n];
  #pragma unroll 8
  for(int k=0;k<SD;k++){
    float sv = s_st[k];
    acc  = fmaf(sv, W1 [k*EM + n], acc);
    accv = fmaf(sv, Vw1[k*EM + n], accv);
  }
  g_sW1[b*EM + n] = acc;
  red[n] = fmaxf(accv, 0.f) * Vw2[n];
  __syncthreads();
  for(int off=128; off>0; off>>=1){
    if(n<off) red[n] += red[n+off];
    __syncthreads();
  }
  if(n==0) g_v[b] = red[0] + Vb2[0];
}

// ============ K2: RNG + permutations + prefix layer-1, emit A-fragment bf16 hi/lo ============
__global__ void k2_layer1(const float* __restrict__ qs, const float* __restrict__ W1){
  int b = blockIdx.x;
  int tid = threadIdx.x;
  __shared__ int   s_inv[SS][AA];
  __shared__ float s_rq[SS*AA*NACT];

  if(tid < SS){
    int s = tid;
    unsigned base = (unsigned)((b*SS + s)*AA);
    float u[AA];
    #pragma unroll
    for(int a=0;a<AA;a++){
      unsigned g = base + a;
      uint32_t o0, o1, bits;
#if RNG_MODE==0
      threefry2x32(0u, g, o0, o1); bits = o0;
#elif RNG_MODE==1
      threefry2x32(0u, g, o0, o1); bits = o1;
#elif RNG_MODE==2
      if(g < 65536u){ threefry2x32(g, g + 65536u, o0, o1); bits = o0; }
      else          { threefry2x32(g - 65536u, g, o0, o1); bits = o1; }
#else
      threefry2x32(0u, g, o0, o1); bits = o0 ^ o1;
#endif
      u[a] = bits_to_unit(bits);
    }
    int ord[AA];
    #pragma unroll
    for(int i=0;i<AA;i++) ord[i]=i;
    for(int i=1;i<AA;i++){
      int oi = ord[i]; float ku = u[oi]; int j=i;
      while(j>0 && u[ord[j-1]] > ku){ ord[j]=ord[j-1]; j--; }
      ord[j]=oi;
    }
    #pragma unroll
    for(int r=0;r<AA;r++) s_inv[s][ord[r]] = r;
    #pragma unroll
    for(int i=0;i<AA;i++) g_pos[base + i] = (unsigned char)ord[i];
  }
  __syncthreads();
  for(int e=tid; e<SS*AA*NACT; e+=blockDim.x){
    int s  = e >> 7;
    int r  = e & 127;
    int j  = r >> 4;
    int na = r & 15;
    s_rq[e] = qs[b*(AA*NACT) + s_inv[s][j]*NACT + na];
  }
  __syncthreads();

  int sgrp = tid >> 6;
  int cg   = tid & 63;   // owns cols 4cg..4cg+3
  const float4 base4 = *(const float4*)&g_sW1[b*EM + cg*4];
  float4 acc[4];
  #pragma unroll
  for(int sl=0;sl<4;sl++) acc[sl] = base4;

  // fragment-store constants for this thread's column group
  const int kblk    = cg >> 2;          // (4cg)/16
  const int lane_off= (cg & 1) * 2;     // ((4cg)%8)/2
  const int regk    = (cg >> 1) & 1;    // ((4cg)%16)/8

  for(int j=0;j<AA;j++){
    #pragma unroll
    for(int na=0;na<NACT;na++){
      float4 w = *(const float4*)&W1[(SD + j*NACT + na)*EM + cg*4];
      #pragma unroll
      for(int sl=0;sl<4;sl++){
        float q = s_rq[(sgrp*4+sl)*128 + j*16 + na];
        acc[sl].x = fmaf(q, w.x, acc[sl].x);
        acc[sl].y = fmaf(q, w.y, acc[sl].y);
        acc[sl].z = fmaf(q, w.z, acc[sl].z);
        acc[sl].w = fmaf(q, w.w, acc[sl].w);
      }
    }
    #pragma unroll
    for(int sl=0;sl<4;sl++){
      int s = sgrp*4+sl;
      int row = s*8 + j;                 // 0..127
      float vx = fmaxf(acc[sl].x, 0.f), vy = fmaxf(acc[sl].y, 0.f);
      float vz = fmaxf(acc[sl].z, 0.f), vw = fmaxf(acc[sl].w, 0.f);
      uint32_t hx,lx,hy,ly,hz,lz,hw,lw;
      split_bf16(vx,hx,lx); split_bf16(vy,hy,ly);
      split_bf16(vz,hz,lz); split_bf16(vw,hw,lw);
      uint32_t hiA = hx | (hy<<16), hiB = hz | (hw<<16);
      uint32_t loA = lx | (ly<<16), loB = lz | (lw<<16);
      int mblk = row >> 4;
      int lane = (row & 7)*4 + lane_off;
      int reg  = ((row >> 3) & 1) + 2*regk;
      size_t aidx = ((((size_t)b*8 + mblk)*16 + kblk)*32 + lane)*4 + reg;
      g_Ah[aidx]   = hiA;  g_Ah[aidx+4] = hiB;   // lane+1 -> +4
      g_Al[aidx]   = loA;  g_Al[aidx+4] = loB;
    }
  }
}

// ============ K3: HMMA GEMM2 (3-pass bf16 split) + fused relu/W3 epilogue ============
__global__ void __launch_bounds__(512,1) k3_mma(const float* __restrict__ b2,
                  const float* __restrict__ W3, const float* __restrict__ b3){
  __shared__ uint32_t sB[2][2][2048];   // [buf][hi/lo][nblk*32+lane)*2+reg]
  __shared__ float b2s[256], w3s[256];
  __shared__ float sred[128][9];
  const int tid  = threadIdx.x;
  const int lane = tid & 31;
  const int warp = tid >> 5;       // 0..15
  const int mblk = warp & 7;
  const int nh   = warp >> 3;      // 0/1 -> n-half
  const int b    = blockIdx.x;

  if (tid < 256){ b2s[tid] = b2[tid]; w3s[tid] = W3[tid]; }
  // stage B chunk 0
  {
    uint4 h = *(const uint4*)&g_Bh[tid*4];
    uint4 l = *(const uint4*)&g_Bl[tid*4];
    *(uint4*)&sB[0][0][tid*4] = h;
    *(uint4*)&sB[0][1][tid*4] = l;
  }

  float d[16][4];
  #pragma unroll
  for(int i=0;i<16;i++){ d[i][0]=0.f; d[i][1]=0.f; d[i][2]=0.f; d[i][3]=0.f; }

  uint32_t ah[4], al[4];
  {
    size_t a0 = ((((size_t)b*8 + mblk)*16 + 0)*32 + lane)*4;
    *(uint4*)ah = *(const uint4*)&g_Ah[a0];
    *(uint4*)al = *(const uint4*)&g_Al[a0];
  }
  __syncthreads();

  for(int kb=0; kb<16; kb++){
    uint4 nh4, nl4;
    uint32_t ahn[4], aln[4];
    if (kb < 15){
      nh4 = *(const uint4*)&g_Bh[(kb+1)*2048 + tid*4];
      nl4 = *(const uint4*)&g_Bl[(kb+1)*2048 + tid*4];
      size_t an = ((((size_t)b*8 + mblk)*16 + (kb+1))*32 + lane)*4;
      *(uint4*)ahn = *(const uint4*)&g_Ah[an];
      *(uint4*)aln = *(const uint4*)&g_Al[an];
    }
    const uint32_t* curh = sB[kb&1][0];
    const uint32_t* curl = sB[kb&1][1];
    #pragma unroll
    for(int nb=0; nb<16; nb++){
      int ng  = nh*16 + nb;
      int off = (ng*32 + lane)*2;
      uint2 bh = *(const uint2*)&curh[off];
      uint2 bl = *(const uint2*)&curl[off];
      mma16816(d[nb], ah, bh.x, bh.y);
      mma16816(d[nb], al, bh.x, bh.y);
      mma16816(d[nb], ah, bl.x, bl.y);
    }
    if (kb < 15){
      *(uint4*)&sB[(kb+1)&1][0][tid*4] = nh4;
      *(uint4*)&sB[(kb+1)&1][1][tid*4] = nl4;
      #pragma unroll
      for(int i=0;i<4;i++){ ah[i]=ahn[i]; al[i]=aln[i]; }
    }
    __syncthreads();
  }

  // epilogue: relu(d + b2) dot W3, per-row partials
  float p0 = 0.f, p1 = 0.f;
  #pragma unroll
  for(int nb=0; nb<16; nb++){
    int c0 = (nh*16 + nb)*8 + (lane&3)*2;
    float w0 = w3s[c0], w1 = w3s[c0+1];
    float bb0 = b2s[c0], bb1 = b2s[c0+1];
    p0 += fmaxf(d[nb][0]+bb0, 0.f)*w0 + fmaxf(d[nb][1]+bb1, 0.f)*w1;
    p1 += fmaxf(d[nb][2]+bb0, 0.f)*w0 + fmaxf(d[nb][3]+bb1, 0.f)*w1;
  }
  int r0 = mblk*16 + (lane>>2);
  sred[r0  ][nh*4 + (lane&3)] = p0;
  sred[r0+8][nh*4 + (lane&3)] = p1;
  __syncthreads();
  if (tid < 128){
    float ssum = b3[0];
    #pragma unroll
    for(int t=0;t<8;t++) ssum += sred[tid][t];
    g_adv[b*128 + tid] = ssum;
  }
}

// ============ K4: shapley[b,i] = v[b] + mean_s adv[b,s,pos[b,s,i]] ============
__global__ void k4_out(float* __restrict__ out){
  int idx = blockIdx.x*blockDim.x + threadIdx.x;
  if(idx >= NB*AA) return;
  int b = idx >> 3, i = idx & 7;
  float sum = 0.f;
  #pragma unroll
  for(int s=0;s<SS;s++){
    int base = (b*SS+s)*AA;
    sum += g_adv[base + (int)g_pos[base+i]];
  }
  out[idx] = g_v[b] + sum * (1.0f/16.0f);
}

extern "C" void kernel_launch(void* const* d_in, const int* in_sizes, int n_in,
                              void* d_out, int out_size){
  const float* states   = (const float*)d_in[0];
  const float* agent_qs = (const float*)d_in[1];
  const float* W1  = (const float*)d_in[2];
  const float* b1  = (const float*)d_in[3];
  const float* W2  = (const float*)d_in[4];
  const float* b2  = (const float*)d_in[5];
  const float* W3  = (const float*)d_in[6];
  const float* b3  = (const float*)d_in[7];
  const float* Vw1 = (const float*)d_in[8];
  const float* Vb1 = (const float*)d_in[9];
  const float* Vw2 = (const float*)d_in[10];
  const float* Vb2 = (const float*)d_in[11];
  float* out = (float*)d_out;

  k0_prepW2<<<128, 256>>>(W2);
  k1_state <<<NB, EM>>>(states, W1, b1, Vw1, Vb1, Vw2, Vb2);
  k2_layer1<<<NB, 256>>>(agent_qs, W1);
  k3_mma   <<<NB, 512>>>(b2, W3, b3);
  k4_out   <<<(NB*AA + 255)/256, 256>>>(out);
}